// round 7
// baseline (speedup 1.0000x reference)
#include <cuda_runtime.h>
#include <cstdint>

// ---------------------------------------------------------------------------
// ChannelMultiHeadAttention, fp32 in/out, tf32 tensor-core compute.
//   energy = x A x^T + xu1 1^T + 1 xu2^T + c0,  A = Wq^T Wk
//   out    = (att @ x) Wv^T + bv
// R7: 2 pairs per warp (2x ILP, shared B-fragment loads), 8 warps/CTA.
// ---------------------------------------------------------------------------

#define FULLMASK 0xffffffffu

__device__ float g_Ax[4608];   // [d][e] stride 72: A (cols 0-63), col64=u1, col65=u2, rest 0
__device__ float g_W[4096];    // W[d][e] = Wv[e][d], tf32-rounded
__device__ float g_wc[256];    // w_c padded 16x16, tf32-rounded (pad = 0)
__device__ float g_c0[1];

__device__ __forceinline__ uint32_t tf32r(float f) {
    uint32_t u; asm("cvt.rna.tf32.f32 %0, %1;" : "=r"(u) : "f"(f)); return u;
}
__device__ __forceinline__ float tf32f(float f) { return __uint_as_float(tf32r(f)); }
__device__ __forceinline__ uint32_t fbits(float f) { return __float_as_uint(f); }

__device__ __forceinline__ void mma8(float* d, uint32_t a0, uint32_t a1, uint32_t a2,
                                     uint32_t a3, uint32_t b0, uint32_t b1) {
    asm("mma.sync.aligned.m16n8k8.row.col.f32.tf32.tf32.f32 "
        "{%0,%1,%2,%3}, {%4,%5,%6,%7}, {%8,%9}, {%0,%1,%2,%3};"
        : "+f"(d[0]), "+f"(d[1]), "+f"(d[2]), "+f"(d[3])
        : "r"(a0), "r"(a1), "r"(a2), "r"(a3), "r"(b0), "r"(b1));
}

// ---------------------------------------------------------------------------
__global__ void prep_kernel(const float* __restrict__ Wq, const float* __restrict__ bq,
                            const float* __restrict__ Wk, const float* __restrict__ bk,
                            const float* __restrict__ Wv, const float* __restrict__ wc) {
    __shared__ float sWq[4096], sWk[4096];
    int t = threadIdx.x;
    for (int i = t; i < 4096; i += 256) { sWq[i] = Wq[i]; sWk[i] = Wk[i]; }
    __syncthreads();
    for (int idx = t; idx < 4096; idx += 256) {
        int d = idx >> 6, e = idx & 63;
        float a = 0.f;
        #pragma unroll 8
        for (int f = 0; f < 64; f++) a += sWq[f * 64 + d] * sWk[f * 64 + e];
        g_Ax[d * 72 + e] = tf32f(a);
        g_W[idx] = tf32f(Wv[e * 64 + d]);   // W[d][e] = Wv[e][d]
    }
    if (t < 256) {
        int a = t >> 4, c = t & 15;
        float v = (a < 14 && c < 14) ? wc[a * 14 + c] : 0.f;
        g_wc[t] = tf32f(v);
    }
    if (t < 64) {
        float s1 = 0.f, s2 = 0.f;
        for (int f = 0; f < 64; f++) {
            s1 += sWq[f * 64 + t] * bk[f];
            s2 += sWk[f * 64 + t] * bq[f];
        }
        g_Ax[t * 72 + 64] = tf32f(s1);
        g_Ax[t * 72 + 65] = tf32f(s2);
        g_Ax[t * 72 + 66] = 0.f; g_Ax[t * 72 + 67] = 0.f;
        g_Ax[t * 72 + 68] = 0.f; g_Ax[t * 72 + 69] = 0.f;
        g_Ax[t * 72 + 70] = 0.f; g_Ax[t * 72 + 71] = 0.f;
    }
    if (t == 0) {
        float c = 0.f;
        for (int f = 0; f < 64; f++) c += bq[f] * bk[f];
        g_c0[0] = c;
    }
}

// ---------------------------------------------------------------------------
// Main: 1 warp = 2 pairs, 8 warps/CTA, 4096 CTAs (exact).
// Per-warp smem: 2 x (16x68 tile + 32 xu) = 2240 fl.
// ---------------------------------------------------------------------------
static const int NW = 8;
static const int SMEM_FLOATS = 9632 + NW * 2240;   // 27552 fl = 110208 B

__global__ __launch_bounds__(32 * NW, 2)
void attn_kernel(const float* __restrict__ x, const float* __restrict__ bv,
                 const float* __restrict__ lng, const float* __restrict__ lnb,
                 float* __restrict__ out) {
    extern __shared__ float sf[];
    float* sA  = sf;            // 64 x 72 (incl. u1/u2 cols)
    float* sW  = sf + 4608;     // 64 x 72
    float* swc = sf + 9216;     // 16 x 20
    float* sbv = sf + 9536;
    float* slg = sf + 9600;
    float* slb = sf + 9616;     // per-warp tiles start at 9632

    const int t = threadIdx.x, w = t >> 5, l = t & 31;
    const int g = l >> 2, tg = l & 3;

    for (int i = t; i < 4608; i += 32 * NW) sA[i] = g_Ax[i];
    for (int i = t; i < 4096; i += 32 * NW) {
        int d = i >> 6, e = i & 63;
        sW[d * 72 + e] = g_W[i];
    }
    if (t < 256) { int a = t >> 4, c = t & 15; swc[a * 20 + c] = g_wc[t]; }
    if (t < 64) sbv[t] = bv[t];
    if (t < 16) {
        slg[t] = (t < 14) ? lng[t] : 0.f;
        slb[t] = (t < 14) ? lnb[t] : 0.f;
    }
    __syncthreads();

    const size_t gw = (size_t)blockIdx.x * NW + w;   // warp job: pairs 2gw, 2gw+1
    const float c0 = g_c0[0];
    float* sxw = sf + 9632 + w * 2240;

    // ---- load both x tiles, round to tf32, zero pad rows 14/15 ----
    #pragma unroll
    for (int P = 0; P < 2; P++) {
        float* sxp = sxw + P * 1120;
        const float4* xg4 = (const float4*)(x + (2 * gw + P) * 896);
        #pragma unroll
        for (int it = 0; it < 7; it++) {
            int k = l + 32 * it;
            float4 v = xg4[k];
            int row = k >> 4, c = (k & 15) << 2;
            *(float4*)(sxp + row * 68 + c) =
                make_float4(tf32f(v.x), tf32f(v.y), tf32f(v.z), tf32f(v.w));
        }
        if (l < 16) {
            float4 z4 = make_float4(0.f, 0.f, 0.f, 0.f);
            *(float4*)(sxp + 14 * 68 + 4 * l) = z4;
            *(float4*)(sxp + 15 * 68 + 4 * l) = z4;
        }
    }
    __syncwarp();

    const int srcA = 4 * g + (tg >> 1);   // quad-local relayout sources
    const int srcB = srcA + 2;
    const bool pr = tg & 1;

    // ---- Y = x @ [A | u1 u2]  (72 MMAs x 2 pairs; B-frags shared) ----
    float dY[2][9][4] = {};
    #pragma unroll
    for (int k0 = 0; k0 < 8; k0++) {
        uint32_t a[2][4];
        #pragma unroll
        for (int P = 0; P < 2; P++) {
            const float* sxp = sxw + P * 1120;
            a[P][0] = fbits(sxp[g * 68 + k0 * 8 + tg]);
            a[P][1] = fbits(sxp[(g + 8) * 68 + k0 * 8 + tg]);
            a[P][2] = fbits(sxp[g * 68 + k0 * 8 + tg + 4]);
            a[P][3] = fbits(sxp[(g + 8) * 68 + k0 * 8 + tg + 4]);
        }
        #pragma unroll
        for (int n0 = 0; n0 < 9; n0++) {
            uint32_t b0 = fbits(sA[(k0 * 8 + tg) * 72 + n0 * 8 + g]);
            uint32_t b1 = fbits(sA[(k0 * 8 + tg + 4) * 72 + n0 * 8 + g]);
            #pragma unroll
            for (int P = 0; P < 2; P++)
                mma8(dY[P][n0], a[P][0], a[P][1], a[P][2], a[P][3], b0, b1);
        }
    }
    // dY[P][8]: xu cols; tg==0 lanes hold (xu1, xu2) for rows g, g+8
    if (tg == 0) {
        #pragma unroll
        for (int P = 0; P < 2; P++) {
            float* sxu1 = sxw + P * 1120 + 1088;
            float* sxu2 = sxw + P * 1120 + 1104;
            sxu1[g] = dY[P][8][0]; sxu2[g] = dY[P][8][1];
            sxu1[g + 8] = dY[P][8][2]; sxu2[g + 8] = dY[P][8][3];
        }
    }
    #pragma unroll
    for (int P = 0; P < 2; P++)
        #pragma unroll
        for (int n0 = 0; n0 < 8; n0++)
            #pragma unroll
            for (int j = 0; j < 4; j++) dY[P][n0][j] = tf32f(dY[P][n0][j]);

    // ---- energy = y @ x^T + biases  (16 MMAs x 2); y A-frags via shuffle ----
    float et[2][2][4];
    {
        float e[2][2][4] = {};
        #pragma unroll
        for (int k0 = 0; k0 < 8; k0++) {
            #pragma unroll
            for (int P = 0; P < 2; P++) {
                const float* sxp = sxw + P * 1120;
                float v0 = __shfl_sync(FULLMASK, dY[P][k0][0], srcA);
                float v1 = __shfl_sync(FULLMASK, dY[P][k0][1], srcA);
                float v2 = __shfl_sync(FULLMASK, dY[P][k0][2], srcA);
                float v3 = __shfl_sync(FULLMASK, dY[P][k0][3], srcA);
                float w0 = __shfl_sync(FULLMASK, dY[P][k0][0], srcB);
                float w1 = __shfl_sync(FULLMASK, dY[P][k0][1], srcB);
                float w2 = __shfl_sync(FULLMASK, dY[P][k0][2], srcB);
                float w3 = __shfl_sync(FULLMASK, dY[P][k0][3], srcB);
                uint32_t a0 = fbits(pr ? v1 : v0);
                uint32_t a1 = fbits(pr ? v3 : v2);
                uint32_t a2 = fbits(pr ? w1 : w0);
                uint32_t a3 = fbits(pr ? w3 : w2);
                #pragma unroll
                for (int nt = 0; nt < 2; nt++) {
                    uint32_t b0 = fbits(sxp[(nt * 8 + g) * 68 + k0 * 8 + tg]);
                    uint32_t b1 = fbits(sxp[(nt * 8 + g) * 68 + k0 * 8 + tg + 4]);
                    mma8(e[P][nt], a0, a1, a2, a3, b0, b1);
                }
            }
        }
        __syncwarp();   // sxu stores visible
        #pragma unroll
        for (int P = 0; P < 2; P++) {
            const float* sxu1 = sxw + P * 1120 + 1088;
            const float* sxu2 = sxw + P * 1120 + 1104;
            float xg0 = sxu1[g] + c0, xg8 = sxu1[g + 8] + c0;
            #pragma unroll
            for (int nt = 0; nt < 2; nt++) {
                int j0 = nt * 8 + 2 * tg;
                float u0 = sxu2[j0], u1v = sxu2[j0 + 1];
                et[P][nt][0] = tf32f(e[P][nt][0] + xg0 + u0);
                et[P][nt][1] = tf32f(e[P][nt][1] + xg0 + u1v);
                et[P][nt][2] = tf32f(e[P][nt][2] + xg8 + u0);
                et[P][nt][3] = tf32f(e[P][nt][3] + xg8 + u1v);
            }
        }
    }

    // ---- mix = w_c @ energy (4 MMAs x 2); A-frags shared; B via shuffle ----
    float att0[2][2], att1[2][2], att2[2][2], att3[2][2];
    {
        const int srcM  = 4 * tg + (g >> 1);
        const int srcM4 = 16 + 4 * tg + (g >> 1);
        const bool pg = g & 1;
        float m[2][2][4] = {};
        #pragma unroll
        for (int k0 = 0; k0 < 2; k0++) {
            uint32_t a0 = fbits(swc[g * 20 + k0 * 8 + tg]);
            uint32_t a1 = fbits(swc[(g + 8) * 20 + k0 * 8 + tg]);
            uint32_t a2 = fbits(swc[g * 20 + k0 * 8 + tg + 4]);
            uint32_t a3 = fbits(swc[(g + 8) * 20 + k0 * 8 + tg + 4]);
            #pragma unroll
            for (int P = 0; P < 2; P++) {
                #pragma unroll
                for (int nt = 0; nt < 2; nt++) {
                    float v0 = __shfl_sync(FULLMASK, et[P][nt][2 * k0], srcM);
                    float v1 = __shfl_sync(FULLMASK, et[P][nt][2 * k0 + 1], srcM);
                    float w0 = __shfl_sync(FULLMASK, et[P][nt][2 * k0], srcM4);
                    float w1 = __shfl_sync(FULLMASK, et[P][nt][2 * k0 + 1], srcM4);
                    uint32_t b0 = fbits(pg ? v1 : v0);
                    uint32_t b1 = fbits(pg ? w1 : w0);
                    mma8(m[P][nt], a0, a1, a2, a3, b0, b1);
                }
            }
        }
        // ---- LayerNorm + softmax in regs (quad reductions), per pair ----
        const bool m3 = (tg == 3);
        float lg0 = slg[2 * tg], lg1 = slg[2 * tg + 1];
        float lg2 = slg[8 + 2 * tg], lg3 = slg[9 + 2 * tg];
        float lb0 = slb[2 * tg], lb1 = slb[2 * tg + 1];
        float lb2 = slb[8 + 2 * tg], lb3 = slb[9 + 2 * tg];
        #pragma unroll
        for (int P = 0; P < 2; P++) {
            #pragma unroll
            for (int rr = 0; rr < 2; rr++) {
                float v0 = m[P][0][2 * rr], v1 = m[P][0][2 * rr + 1];
                float v2 = m[P][1][2 * rr], v3 = m[P][1][2 * rr + 1];
                float s = v0 + v1 + (m3 ? 0.f : (v2 + v3));
                s += __shfl_xor_sync(FULLMASK, s, 1);
                s += __shfl_xor_sync(FULLMASK, s, 2);
                float mu = s * (1.f / 14.f);
                float d0 = v0 - mu, d1 = v1 - mu, d2 = v2 - mu, d3 = v3 - mu;
                float q = d0 * d0 + d1 * d1 + (m3 ? 0.f : (d2 * d2 + d3 * d3));
                q += __shfl_xor_sync(FULLMASK, q, 1);
                q += __shfl_xor_sync(FULLMASK, q, 2);
                float rsv = rsqrtf(q * (1.f / 14.f) + 1e-5f);
                float t0 = (d0 * rsv * lg0 + lb0) * 0.125f;
                float t1 = (d1 * rsv * lg1 + lb1) * 0.125f;
                float t2 = (d2 * rsv * lg2 + lb2) * 0.125f;
                float t3 = (d3 * rsv * lg3 + lb3) * 0.125f;
                float mx = fmaxf(fmaxf(t0, t1), m3 ? -1e30f : fmaxf(t2, t3));
                mx = fmaxf(mx, __shfl_xor_sync(FULLMASK, mx, 1));
                mx = fmaxf(mx, __shfl_xor_sync(FULLMASK, mx, 2));
                float e0 = __expf(t0 - mx), e1 = __expf(t1 - mx);
                float e2 = m3 ? 0.f : __expf(t2 - mx);
                float e3 = m3 ? 0.f : __expf(t3 - mx);
                float ss = e0 + e1 + e2 + e3;
                ss += __shfl_xor_sync(FULLMASK, ss, 1);
                ss += __shfl_xor_sync(FULLMASK, ss, 2);
                float inv = 1.f / ss;
                att0[P][rr] = tf32f(e0 * inv); att1[P][rr] = tf32f(e1 * inv);
                att2[P][rr] = tf32f(e2 * inv); att3[P][rr] = tf32f(e3 * inv);
            }
        }
    }

    // ---- z = att @ x  (16 MMAs x 2); att A-frags via shuffle ----
    float zd[2][8][4] = {};
    #pragma unroll
    for (int k0 = 0; k0 < 2; k0++) {
        #pragma unroll
        for (int P = 0; P < 2; P++) {
            const float* sxp = sxw + P * 1120;
            float p0, p1, q0, q1, p2, p3, q2, q3;
            if (k0 == 0) {
                p0 = __shfl_sync(FULLMASK, att0[P][0], srcA);
                p1 = __shfl_sync(FULLMASK, att1[P][0], srcA);
                p2 = __shfl_sync(FULLMASK, att0[P][1], srcA);
                p3 = __shfl_sync(FULLMASK, att1[P][1], srcA);
                q0 = __shfl_sync(FULLMASK, att0[P][0], srcB);
                q1 = __shfl_sync(FULLMASK, att1[P][0], srcB);
                q2 = __shfl_sync(FULLMASK, att0[P][1], srcB);
                q3 = __shfl_sync(FULLMASK, att1[P][1], srcB);
            } else {
                p0 = __shfl_sync(FULLMASK, att2[P][0], srcA);
                p1 = __shfl_sync(FULLMASK, att3[P][0], srcA);
                p2 = __shfl_sync(FULLMASK, att2[P][1], srcA);
                p3 = __shfl_sync(FULLMASK, att3[P][1], srcA);
                q0 = __shfl_sync(FULLMASK, att2[P][0], srcB);
                q1 = __shfl_sync(FULLMASK, att3[P][0], srcB);
                q2 = __shfl_sync(FULLMASK, att2[P][1], srcB);
                q3 = __shfl_sync(FULLMASK, att3[P][1], srcB);
            }
            uint32_t a0 = fbits(pr ? p1 : p0);
            uint32_t a1 = fbits(pr ? p3 : p2);
            uint32_t a2 = fbits(pr ? q1 : q0);
            uint32_t a3 = fbits(pr ? q3 : q2);
            #pragma unroll
            for (int n0 = 0; n0 < 8; n0++) {
                uint32_t b0 = fbits(sxp[(k0 * 8 + tg) * 68 + n0 * 8 + g]);
                uint32_t b1 = fbits(sxp[(k0 * 8 + tg + 4) * 68 + n0 * 8 + g]);
                mma8(zd[P][n0], a0, a1, a2, a3, b0, b1);
            }
        }
    }
    __syncwarp();   // all x reads done; reuse sx tiles for z
    #pragma unroll
    for (int P = 0; P < 2; P++) {
        float* sxp = sxw + P * 1120;
        #pragma unroll
        for (int n0 = 0; n0 < 8; n0++) {
            *(float2*)(sxp + g * 68 + n0 * 8 + 2 * tg) =
                make_float2(tf32f(zd[P][n0][0]), tf32f(zd[P][n0][1]));
            *(float2*)(sxp + (g + 8) * 68 + n0 * 8 + 2 * tg) =
                make_float2(tf32f(zd[P][n0][2]), tf32f(zd[P][n0][3]));
        }
    }
    __syncwarp();

    // ---- out = z @ Wv^T + bv  (64 MMAs x 2; B-frags shared) ----
    {
        float od[2][8][4] = {};
        #pragma unroll
        for (int k0 = 0; k0 < 8; k0++) {
            uint32_t a[2][4];
            #pragma unroll
            for (int P = 0; P < 2; P++) {
                const float* sxp = sxw + P * 1120;
                a[P][0] = fbits(sxp[g * 68 + k0 * 8 + tg]);
                a[P][1] = fbits(sxp[(g + 8) * 68 + k0 * 8 + tg]);
                a[P][2] = fbits(sxp[g * 68 + k0 * 8 + tg + 4]);
                a[P][3] = fbits(sxp[(g + 8) * 68 + k0 * 8 + tg + 4]);
            }
            #pragma unroll
            for (int n0 = 0; n0 < 8; n0++) {
                uint32_t b0 = fbits(sW[(k0 * 8 + tg) * 72 + n0 * 8 + g]);
                uint32_t b1 = fbits(sW[(k0 * 8 + tg + 4) * 72 + n0 * 8 + g]);
                #pragma unroll
                for (int P = 0; P < 2; P++)
                    mma8(od[P][n0], a[P][0], a[P][1], a[P][2], a[P][3], b0, b1);
            }
        }
        #pragma unroll
        for (int P = 0; P < 2; P++) {
            float* og = out + (2 * gw + P) * 896;
            #pragma unroll
            for (int n0 = 0; n0 < 8; n0++) {
                int cc = n0 * 8 + 2 * tg;
                float2 bb = *(const float2*)(sbv + cc);
                *(float2*)(og + g * 64 + cc) =
                    make_float2(od[P][n0][0] + bb.x, od[P][n0][1] + bb.y);
                if (g < 6)
                    *(float2*)(og + (g + 8) * 64 + cc) =
                        make_float2(od[P][n0][2] + bb.x, od[P][n0][3] + bb.y);
            }
        }
    }
}

// ---------------------------------------------------------------------------
extern "C" void kernel_launch(void* const* d_in, const int* in_sizes, int n_in,
                              void* d_out, int out_size) {
    const float* x   = (const float*)d_in[0];
    const float* wc  = (const float*)d_in[1];
    const float* Wq  = (const float*)d_in[2];
    const float* bq  = (const float*)d_in[3];
    const float* Wk  = (const float*)d_in[4];
    const float* bk  = (const float*)d_in[5];
    const float* Wv  = (const float*)d_in[6];
    const float* bv  = (const float*)d_in[7];
    const float* lng = (const float*)d_in[8];
    const float* lnb = (const float*)d_in[9];
    float* out = (float*)d_out;

    cudaFuncSetAttribute(attn_kernel, cudaFuncAttributeMaxDynamicSharedMemorySize,
                         SMEM_FLOATS * 4);

    prep_kernel<<<1, 256>>>(Wq, bq, Wk, bk, Wv, wc);
    attn_kernel<<<4096, 32 * NW, SMEM_FLOATS * 4>>>(x, bv, lng, lnb, out);
}

// round 8
// speedup vs baseline: 1.1127x; 1.1127x over previous
#include <cuda_runtime.h>
#include <cstdint>

// ---------------------------------------------------------------------------
// ChannelMultiHeadAttention, fp32 in/out, tf32 tensor-core compute.
//   energy = x A x^T + xu1 1^T + 1 xu2^T + c0,  A = Wq^T Wk
//   out    = (att @ x) Wv^T + bv
// R8: frag-packed float2 B-matrices (LDS.64 per b0/b1 pair), xu fold,
//     8 warps/CTA x 3 CTA/SM = 24 warps/SM, exact 8192-CTA grid.
// ---------------------------------------------------------------------------

#define FULLMASK 0xffffffffu

// packed: g_Ap[((k0*4+tg)*76 + e)*2 + h] = tf32(A[k0*8+tg+4*h][e])
//   cols 0-63 = A = Wq^T Wk, col 64 = u1, col 65 = u2, 66-71 = 0
__device__ float g_Ap[4864];
// same packing for W[d][e] = Wv[e][d]  (cols 0-63 used)
__device__ float g_Wp[4864];
__device__ float g_wc[256];    // w_c padded 16x16, tf32-rounded (pad = 0)
__device__ float g_c0[1];

__device__ __forceinline__ uint32_t tf32r(float f) {
    uint32_t u; asm("cvt.rna.tf32.f32 %0, %1;" : "=r"(u) : "f"(f)); return u;
}
__device__ __forceinline__ float tf32f(float f) { return __uint_as_float(tf32r(f)); }
__device__ __forceinline__ uint32_t fbits(float f) { return __float_as_uint(f); }

__device__ __forceinline__ void mma8(float* d, uint32_t a0, uint32_t a1, uint32_t a2,
                                     uint32_t a3, uint32_t b0, uint32_t b1) {
    asm("mma.sync.aligned.m16n8k8.row.col.f32.tf32.tf32.f32 "
        "{%0,%1,%2,%3}, {%4,%5,%6,%7}, {%8,%9}, {%0,%1,%2,%3};"
        : "+f"(d[0]), "+f"(d[1]), "+f"(d[2]), "+f"(d[3])
        : "r"(a0), "r"(a1), "r"(a2), "r"(a3), "r"(b0), "r"(b1));
}

// ---------------------------------------------------------------------------
__global__ void prep_kernel(const float* __restrict__ Wq, const float* __restrict__ bq,
                            const float* __restrict__ Wk, const float* __restrict__ bk,
                            const float* __restrict__ Wv, const float* __restrict__ wc) {
    __shared__ float sWq[4096], sWk[4096];
    int t = threadIdx.x;
    for (int i = t; i < 4096; i += 256) { sWq[i] = Wq[i]; sWk[i] = Wk[i]; }
    __syncthreads();
    for (int idx = t; idx < 4096; idx += 256) {
        int d = idx >> 6, e = idx & 63;
        float a = 0.f;
        #pragma unroll 8
        for (int f = 0; f < 64; f++) a += sWq[f * 64 + d] * sWk[f * 64 + e];
        int k0 = d >> 3, tt = d & 7;
        int slot = ((k0 * 4 + (tt & 3)) * 76 + e) * 2 + (tt >> 2);
        g_Ap[slot] = tf32f(a);
        g_Wp[slot] = tf32f(Wv[e * 64 + d]);   // W[d][e] = Wv[e][d]
    }
    if (t < 256) {
        int a = t >> 4, c = t & 15;
        float v = (a < 14 && c < 14) ? wc[a * 14 + c] : 0.f;
        g_wc[t] = tf32f(v);
    }
    if (t < 64) {
        int d = t;
        float s1 = 0.f, s2 = 0.f;
        for (int f = 0; f < 64; f++) {
            s1 += sWq[f * 64 + d] * bk[f];
            s2 += sWk[f * 64 + d] * bq[f];
        }
        int k0 = d >> 3, tt = d & 7;
        int base = (k0 * 4 + (tt & 3)) * 76;
        int h = tt >> 2;
        g_Ap[(base + 64) * 2 + h] = tf32f(s1);
        g_Ap[(base + 65) * 2 + h] = tf32f(s2);
        #pragma unroll
        for (int e = 66; e < 72; e++) g_Ap[(base + e) * 2 + h] = 0.f;
    }
    if (t == 0) {
        float c = 0.f;
        for (int f = 0; f < 64; f++) c += bq[f] * bk[f];
        g_c0[0] = c;
    }
}

// ---------------------------------------------------------------------------
// Main: 1 warp = 1 pair, 8 warps/CTA, 8192 CTAs (exact), 3 CTA/SM.
// smem: pA 4864 + pW 4864 + swc 320 + consts 96 + 8 x 1120 = 19104 fl (76.4 KB)
// ---------------------------------------------------------------------------
static const int NW = 8;
static const int SMEM_FLOATS = 10144 + NW * 1120;   // 19104 fl = 76416 B

__global__ __launch_bounds__(32 * NW, 3)
void attn_kernel(const float* __restrict__ x, const float* __restrict__ bv,
                 const float* __restrict__ lng, const float* __restrict__ lnb,
                 float* __restrict__ out) {
    extern __shared__ float sf[];
    float* sAp = sf;            // 4864 (32 rows x 76 float2)
    float* sWp = sf + 4864;     // 4864
    float* swc = sf + 9728;     // 16 x 20
    float* sbv = sf + 10048;
    float* slg = sf + 10112;
    float* slb = sf + 10128;    // per-warp tiles start at 10144

    const int t = threadIdx.x, w = t >> 5, l = t & 31;
    const int g = l >> 2, tg = l & 3;

    for (int i = t; i < 4864; i += 32 * NW) { sAp[i] = g_Ap[i]; sWp[i] = g_Wp[i]; }
    if (t < 256) { int a = t >> 4, c = t & 15; swc[a * 20 + c] = g_wc[t]; }
    if (t < 64) sbv[t] = bv[t];
    if (t < 16) {
        slg[t] = (t < 14) ? lng[t] : 0.f;
        slb[t] = (t < 14) ? lnb[t] : 0.f;
    }
    __syncthreads();

    const size_t pair = (size_t)blockIdx.x * NW + w;
    const float c0 = g_c0[0];

    float* sx   = sf + 10144 + w * 1120;   // 16 x 68
    float* sxu1 = sx + 1088;               // 16
    float* sxu2 = sx + 1104;               // 16
    const float2* pA = (const float2*)sAp;
    const float2* pW = (const float2*)sWp;

    // ---- load x tile, round to tf32, zero pad rows 14/15 ----
    const float4* xg4 = (const float4*)(x + pair * 896);
    #pragma unroll
    for (int it = 0; it < 7; it++) {
        int k = l + 32 * it;
        float4 v = xg4[k];
        int row = k >> 4, c = (k & 15) << 2;
        *(float4*)(sx + row * 68 + c) =
            make_float4(tf32f(v.x), tf32f(v.y), tf32f(v.z), tf32f(v.w));
    }
    if (l < 16) {
        float4 z4 = make_float4(0.f, 0.f, 0.f, 0.f);
        *(float4*)(sx + 14 * 68 + 4 * l) = z4;
        *(float4*)(sx + 15 * 68 + 4 * l) = z4;
    }
    __syncwarp();

    const int srcA = 4 * g + (tg >> 1);   // quad-local relayout sources
    const int srcB = srcA + 2;
    const bool pr = tg & 1;

    // ---- Y = x @ [A | u1 u2]  (72 MMAs); packed LDS.64 B-frags ----
    float dY[9][4] = {};
    #pragma unroll
    for (int k0 = 0; k0 < 8; k0++) {
        uint32_t a0 = fbits(sx[g * 68 + k0 * 8 + tg]);
        uint32_t a1 = fbits(sx[(g + 8) * 68 + k0 * 8 + tg]);
        uint32_t a2 = fbits(sx[g * 68 + k0 * 8 + tg + 4]);
        uint32_t a3 = fbits(sx[(g + 8) * 68 + k0 * 8 + tg + 4]);
        const float2* pAr = pA + (k0 * 4 + tg) * 76 + g;
        #pragma unroll
        for (int n0 = 0; n0 < 9; n0++) {
            float2 b = pAr[n0 * 8];
            mma8(dY[n0], a0, a1, a2, a3, fbits(b.x), fbits(b.y));
        }
    }
    // dY[8]: cols 64-71; tg==0 lanes hold (xu1, xu2) for rows g, g+8
    if (tg == 0) {
        sxu1[g] = dY[8][0]; sxu2[g] = dY[8][1];
        sxu1[g + 8] = dY[8][2]; sxu2[g + 8] = dY[8][3];
    }
    #pragma unroll
    for (int n0 = 0; n0 < 8; n0++)
        #pragma unroll
        for (int j = 0; j < 4; j++) dY[n0][j] = tf32f(dY[n0][j]);

    // ---- energy = y @ x^T + biases  (16 MMAs); y A-frags via shuffle ----
    float et[2][4];
    {
        float e[2][4] = {};
        #pragma unroll
        for (int k0 = 0; k0 < 8; k0++) {
            float v0 = __shfl_sync(FULLMASK, dY[k0][0], srcA);
            float v1 = __shfl_sync(FULLMASK, dY[k0][1], srcA);
            float v2 = __shfl_sync(FULLMASK, dY[k0][2], srcA);
            float v3 = __shfl_sync(FULLMASK, dY[k0][3], srcA);
            float w0 = __shfl_sync(FULLMASK, dY[k0][0], srcB);
            float w1 = __shfl_sync(FULLMASK, dY[k0][1], srcB);
            float w2 = __shfl_sync(FULLMASK, dY[k0][2], srcB);
            float w3 = __shfl_sync(FULLMASK, dY[k0][3], srcB);
            uint32_t a0 = fbits(pr ? v1 : v0);
            uint32_t a1 = fbits(pr ? v3 : v2);
            uint32_t a2 = fbits(pr ? w1 : w0);
            uint32_t a3 = fbits(pr ? w3 : w2);
            #pragma unroll
            for (int nt = 0; nt < 2; nt++) {
                uint32_t b0 = fbits(sx[(nt * 8 + g) * 68 + k0 * 8 + tg]);
                uint32_t b1 = fbits(sx[(nt * 8 + g) * 68 + k0 * 8 + tg + 4]);
                mma8(e[nt], a0, a1, a2, a3, b0, b1);
            }
        }
        __syncwarp();   // sxu1/sxu2 stores visible
        float xg0 = sxu1[g] + c0, xg8 = sxu1[g + 8] + c0;
        #pragma unroll
        for (int nt = 0; nt < 2; nt++) {
            int j0 = nt * 8 + 2 * tg;
            float u0 = sxu2[j0], u1v = sxu2[j0 + 1];
            et[nt][0] = tf32f(e[nt][0] + xg0 + u0);
            et[nt][1] = tf32f(e[nt][1] + xg0 + u1v);
            et[nt][2] = tf32f(e[nt][2] + xg8 + u0);
            et[nt][3] = tf32f(e[nt][3] + xg8 + u1v);
        }
    }

    // ---- mix = w_c @ energy (4 MMAs); energy B-frags via shuffle ----
    float att0[2], att1[2], att2[2], att3[2];
    {
        const int srcM  = 4 * tg + (g >> 1);       // row 8k0+tg source
        const int srcM4 = 16 + 4 * tg + (g >> 1);  // row 8k0+tg+4 source
        const bool pg = g & 1;
        float m[2][4] = {};
        #pragma unroll
        for (int k0 = 0; k0 < 2; k0++) {
            uint32_t a0 = fbits(swc[g * 20 + k0 * 8 + tg]);
            uint32_t a1 = fbits(swc[(g + 8) * 20 + k0 * 8 + tg]);
            uint32_t a2 = fbits(swc[g * 20 + k0 * 8 + tg + 4]);
            uint32_t a3 = fbits(swc[(g + 8) * 20 + k0 * 8 + tg + 4]);
            #pragma unroll
            for (int nt = 0; nt < 2; nt++) {
                float v0 = __shfl_sync(FULLMASK, et[nt][2 * k0], srcM);
                float v1 = __shfl_sync(FULLMASK, et[nt][2 * k0 + 1], srcM);
                float w0 = __shfl_sync(FULLMASK, et[nt][2 * k0], srcM4);
                float w1 = __shfl_sync(FULLMASK, et[nt][2 * k0 + 1], srcM4);
                uint32_t b0 = fbits(pg ? v1 : v0);
                uint32_t b1 = fbits(pg ? w1 : w0);
                mma8(m[nt], a0, a1, a2, a3, b0, b1);
            }
        }
        // ---- LayerNorm + softmax in regs (quad reductions) ----
        const bool m3 = (tg == 3);   // cols 14,15
        float lg0 = slg[2 * tg], lg1 = slg[2 * tg + 1];
        float lg2 = slg[8 + 2 * tg], lg3 = slg[9 + 2 * tg];
        float lb0 = slb[2 * tg], lb1 = slb[2 * tg + 1];
        float lb2 = slb[8 + 2 * tg], lb3 = slb[9 + 2 * tg];
        #pragma unroll
        for (int rr = 0; rr < 2; rr++) {
            float v0 = m[0][2 * rr], v1 = m[0][2 * rr + 1];
            float v2 = m[1][2 * rr], v3 = m[1][2 * rr + 1];
            float s = v0 + v1 + (m3 ? 0.f : (v2 + v3));
            s += __shfl_xor_sync(FULLMASK, s, 1);
            s += __shfl_xor_sync(FULLMASK, s, 2);
            float mu = s * (1.f / 14.f);
            float d0 = v0 - mu, d1 = v1 - mu, d2 = v2 - mu, d3 = v3 - mu;
            float q = d0 * d0 + d1 * d1 + (m3 ? 0.f : (d2 * d2 + d3 * d3));
            q += __shfl_xor_sync(FULLMASK, q, 1);
            q += __shfl_xor_sync(FULLMASK, q, 2);
            float rsv = rsqrtf(q * (1.f / 14.f) + 1e-5f);
            float t0 = (d0 * rsv * lg0 + lb0) * 0.125f;
            float t1 = (d1 * rsv * lg1 + lb1) * 0.125f;
            float t2 = (d2 * rsv * lg2 + lb2) * 0.125f;
            float t3 = (d3 * rsv * lg3 + lb3) * 0.125f;
            float mx = fmaxf(fmaxf(t0, t1), m3 ? -1e30f : fmaxf(t2, t3));
            mx = fmaxf(mx, __shfl_xor_sync(FULLMASK, mx, 1));
            mx = fmaxf(mx, __shfl_xor_sync(FULLMASK, mx, 2));
            float e0 = __expf(t0 - mx), e1 = __expf(t1 - mx);
            float e2 = m3 ? 0.f : __expf(t2 - mx);
            float e3 = m3 ? 0.f : __expf(t3 - mx);
            float ss = e0 + e1 + e2 + e3;
            ss += __shfl_xor_sync(FULLMASK, ss, 1);
            ss += __shfl_xor_sync(FULLMASK, ss, 2);
            float inv = 1.f / ss;
            att0[rr] = tf32f(e0 * inv); att1[rr] = tf32f(e1 * inv);
            att2[rr] = tf32f(e2 * inv); att3[rr] = tf32f(e3 * inv);
        }
    }

    // ---- z = att @ x  (16 MMAs); att A-frags via shuffle ----
    float zd[8][4] = {};
    #pragma unroll
    for (int k0 = 0; k0 < 2; k0++) {
        float p0, p1, q0, q1, p2, p3, q2, q3;
        if (k0 == 0) {
            p0 = __shfl_sync(FULLMASK, att0[0], srcA);
            p1 = __shfl_sync(FULLMASK, att1[0], srcA);
            p2 = __shfl_sync(FULLMASK, att0[1], srcA);
            p3 = __shfl_sync(FULLMASK, att1[1], srcA);
            q0 = __shfl_sync(FULLMASK, att0[0], srcB);
            q1 = __shfl_sync(FULLMASK, att1[0], srcB);
            q2 = __shfl_sync(FULLMASK, att0[1], srcB);
            q3 = __shfl_sync(FULLMASK, att1[1], srcB);
        } else {
            p0 = __shfl_sync(FULLMASK, att2[0], srcA);
            p1 = __shfl_sync(FULLMASK, att3[0], srcA);
            p2 = __shfl_sync(FULLMASK, att2[1], srcA);
            p3 = __shfl_sync(FULLMASK, att3[1], srcA);
            q0 = __shfl_sync(FULLMASK, att2[0], srcB);
            q1 = __shfl_sync(FULLMASK, att3[0], srcB);
            q2 = __shfl_sync(FULLMASK, att2[1], srcB);
            q3 = __shfl_sync(FULLMASK, att3[1], srcB);
        }
        uint32_t a0 = fbits(pr ? p1 : p0);
        uint32_t a1 = fbits(pr ? p3 : p2);
        uint32_t a2 = fbits(pr ? q1 : q0);
        uint32_t a3 = fbits(pr ? q3 : q2);
        #pragma unroll
        for (int n0 = 0; n0 < 8; n0++) {
            uint32_t b0 = fbits(sx[(k0 * 8 + tg) * 68 + n0 * 8 + g]);
            uint32_t b1 = fbits(sx[(k0 * 8 + tg + 4) * 68 + n0 * 8 + g]);
            mma8(zd[n0], a0, a1, a2, a3, b0, b1);
        }
    }
    __syncwarp();   // all x reads done; reuse sx for z
    #pragma unroll
    for (int n0 = 0; n0 < 8; n0++) {
        *(float2*)(sx + g * 68 + n0 * 8 + 2 * tg) =
            make_float2(tf32f(zd[n0][0]), tf32f(zd[n0][1]));
        *(float2*)(sx + (g + 8) * 68 + n0 * 8 + 2 * tg) =
            make_float2(tf32f(zd[n0][2]), tf32f(zd[n0][3]));
    }
    __syncwarp();

    // ---- out = z @ Wv^T + bv  (64 MMAs); packed LDS.64 B-frags ----
    {
        float od[8][4] = {};
        #pragma unroll
        for (int k0 = 0; k0 < 8; k0++) {
            uint32_t a0 = fbits(sx[g * 68 + k0 * 8 + tg]);
            uint32_t a1 = fbits(sx[(g + 8) * 68 + k0 * 8 + tg]);
            uint32_t a2 = fbits(sx[g * 68 + k0 * 8 + tg + 4]);
            uint32_t a3 = fbits(sx[(g + 8) * 68 + k0 * 8 + tg + 4]);
            const float2* pWr = pW + (k0 * 4 + tg) * 76 + g;
            #pragma unroll
            for (int n0 = 0; n0 < 8; n0++) {
                float2 b = pWr[n0 * 8];
                mma8(od[n0], a0, a1, a2, a3, fbits(b.x), fbits(b.y));
            }
        }
        float* og = out + pair * 896;
        #pragma unroll
        for (int n0 = 0; n0 < 8; n0++) {
            int cc = n0 * 8 + 2 * tg;
            float2 bb = *(const float2*)(sbv + cc);
            *(float2*)(og + g * 64 + cc) =
                make_float2(od[n0][0] + bb.x, od[n0][1] + bb.y);
            if (g < 6)
                *(float2*)(og + (g + 8) * 64 + cc) =
                    make_float2(od[n0][2] + bb.x, od[n0][3] + bb.y);
        }
    }
}

// ---------------------------------------------------------------------------
extern "C" void kernel_launch(void* const* d_in, const int* in_sizes, int n_in,
                              void* d_out, int out_size) {
    const float* x   = (const float*)d_in[0];
    const float* wc  = (const float*)d_in[1];
    const float* Wq  = (const float*)d_in[2];
    const float* bq  = (const float*)d_in[3];
    const float* Wk  = (const float*)d_in[4];
    const float* bk  = (const float*)d_in[5];
    const float* Wv  = (const float*)d_in[6];
    const float* bv  = (const float*)d_in[7];
    const float* lng = (const float*)d_in[8];
    const float* lnb = (const float*)d_in[9];
    float* out = (float*)d_out;

    cudaFuncSetAttribute(attn_kernel, cudaFuncAttributeMaxDynamicSharedMemorySize,
                         SMEM_FLOATS * 4);

    prep_kernel<<<1, 256>>>(Wq, bq, Wk, bk, Wv, wc);
    attn_kernel<<<8192, 32 * NW, SMEM_FLOATS * 4>>>(x, bv, lng, lnb, out);
}

// round 9
// speedup vs baseline: 2.0283x; 1.8228x over previous
#include <cuda_runtime.h>
#include <cuda_fp16.h>
#include <cstdint>

// ---------------------------------------------------------------------------
// ChannelMultiHeadAttention, fp32 in/out, fp16 tensor-core compute (m16n8k16).
//   energy = x A x^T + xu1 1^T + 1 xu2^T + c0,  A = Wq^T Wk
//   out    = att @ v + bv,  v = x @ Wv^T   (computed as vT C-frags)
// R9: fp16 MMA halves instruction count; k16 frag geometry makes y->energy
//     and v->out relayouts lane-local (zero shuffles, zero smem round-trips).
// ---------------------------------------------------------------------------

#define FULLMASK 0xffffffffu

// Packed B-frags of [A | u1 u2 | 0pad]: entry[(k0*4+tq)*84 + e] =
//   {h2(A[16k0+2tq][e], A[16k0+2tq+1][e]), h2(A[16k0+2tq+8][e], A[16k0+2tq+9][e])}
__device__ uint2  g_PA[16 * 84];
// Packed A-frags of Wv: entry[(mt*8+q)*36 + cp] =
//   {h2(Wv[16mt+q][2cp], [2cp+1]), h2(Wv[16mt+q+8][2cp], [2cp+1])}
__device__ uint2  g_PW[32 * 36];
__device__ __half g_wch[256];     // wc padded 16x16 fp16
__device__ float  g_Af[4096], g_u1f[64], g_u2f[64], g_c0[1];

__device__ __forceinline__ uint32_t h2u(float a, float b) {
    __half2 h = __floats2half2_rn(a, b);
    return *(uint32_t*)&h;
}

__device__ __forceinline__ void mma16(float* d, uint32_t a0, uint32_t a1, uint32_t a2,
                                      uint32_t a3, uint32_t b0, uint32_t b1) {
    asm("mma.sync.aligned.m16n8k16.row.col.f32.f16.f16.f32 "
        "{%0,%1,%2,%3}, {%4,%5,%6,%7}, {%8,%9}, {%0,%1,%2,%3};"
        : "+f"(d[0]), "+f"(d[1]), "+f"(d[2]), "+f"(d[3])
        : "r"(a0), "r"(a1), "r"(a2), "r"(a3), "r"(b0), "r"(b1));
}

// ---------------------------------------------------------------------------
__global__ void prep_kernel(const float* __restrict__ Wq, const float* __restrict__ bq,
                            const float* __restrict__ Wk, const float* __restrict__ bk,
                            const float* __restrict__ Wv, const float* __restrict__ wc) {
    __shared__ float sWq[4096], sWk[4096];
    int t = threadIdx.x;
    for (int i = t; i < 4096; i += 256) { sWq[i] = Wq[i]; sWk[i] = Wk[i]; }
    __syncthreads();
    for (int idx = t; idx < 4096; idx += 256) {
        int d = idx >> 6, e = idx & 63;
        float a = 0.f;
        #pragma unroll 8
        for (int f = 0; f < 64; f++) a += sWq[f * 64 + d] * sWk[f * 64 + e];
        g_Af[idx] = a;
    }
    if (t < 64) {
        float s1 = 0.f, s2 = 0.f;
        for (int f = 0; f < 64; f++) {
            s1 += sWq[f * 64 + t] * bk[f];
            s2 += sWk[f * 64 + t] * bq[f];
        }
        g_u1f[t] = s1; g_u2f[t] = s2;
    }
    if (t < 256) {
        int a = t >> 4, c = t & 15;
        float v = (a < 14 && c < 14) ? wc[a * 14 + c] : 0.f;
        g_wch[t] = __float2half_rn(v);
    }
    if (t == 0) {
        float c = 0.f;
        for (int f = 0; f < 64; f++) c += bq[f] * bk[f];
        g_c0[0] = c;
    }
    __syncthreads();

    // pack P_A (cols 0-63 = A, 64 = u1, 65 = u2, 66-71 = 0)
    for (int idx = t; idx < 16 * 72; idx += 256) {
        int kq = idx / 72, e = idx % 72;
        int k0 = kq >> 2, tq = kq & 3;
        int db = 16 * k0 + 2 * tq;
        float v0, v1, v2, v3;
        if (e < 64) {
            v0 = g_Af[db * 64 + e];       v1 = g_Af[(db + 1) * 64 + e];
            v2 = g_Af[(db + 8) * 64 + e]; v3 = g_Af[(db + 9) * 64 + e];
        } else if (e == 64) {
            v0 = g_u1f[db]; v1 = g_u1f[db + 1]; v2 = g_u1f[db + 8]; v3 = g_u1f[db + 9];
        } else if (e == 65) {
            v0 = g_u2f[db]; v1 = g_u2f[db + 1]; v2 = g_u2f[db + 8]; v3 = g_u2f[db + 9];
        } else { v0 = v1 = v2 = v3 = 0.f; }
        g_PA[kq * 84 + e] = make_uint2(h2u(v0, v1), h2u(v2, v3));
    }
    // pack P_W (A-operand of vT GEMM = Wv row-major)
    for (int idx = t; idx < 32 * 36; idx += 256) {
        int r = idx / 36, cp = idx % 36;
        int mt = r >> 3, q = r & 7;
        uint2 u = make_uint2(0u, 0u);
        if (cp < 32) {
            int e0 = 16 * mt + q;
            u.x = h2u(Wv[e0 * 64 + 2 * cp], Wv[e0 * 64 + 2 * cp + 1]);
            u.y = h2u(Wv[(e0 + 8) * 64 + 2 * cp], Wv[(e0 + 8) * 64 + 2 * cp + 1]);
        }
        g_PW[idx] = u;
    }
}

// ---------------------------------------------------------------------------
// Main: 1 warp = 1 pair, 8 warps/CTA, 8192 CTAs (exact).
// smem: PA 10752 + PW 9216 + wc 768 + bv 256 + ln 128 + 8 x 2432 = 40576 B
// ---------------------------------------------------------------------------
static const int NW = 8;
static const int SMEM_BYTES = 10752 + 9216 + 768 + 256 + 128 + NW * 2432;  // 40576

__global__ __launch_bounds__(32 * NW, 3)
void attn_kernel(const float* __restrict__ x, const float* __restrict__ bv,
                 const float* __restrict__ lng, const float* __restrict__ lnb,
                 float* __restrict__ out) {
    extern __shared__ __align__(16) unsigned char smraw[];
    uint2*  sPA  = (uint2*)smraw;                    // 16*84
    uint2*  sPW  = sPA + 16 * 84;                    // 32*36
    __half* swch = (__half*)(sPW + 32 * 36);         // 16 x 24
    float*  sbv  = (float*)(swch + 384);             // 64
    float*  slg  = sbv + 64;                         // 16
    float*  slb  = slg + 16;                         // 16
    __half* stil = (__half*)(slb + 16);              // NW x 1216 halves

    const int t = threadIdx.x, w = t >> 5, l = t & 31;
    const int g = l >> 2, tg = l & 3;

    for (int i = t; i < 16 * 84; i += 32 * NW) sPA[i] = g_PA[i];
    for (int i = t; i < 32 * 36; i += 32 * NW) sPW[i] = g_PW[i];
    if (t < 256) swch[(t >> 4) * 24 + (t & 15)] = g_wch[t];
    if (t < 64) sbv[t] = bv[t];
    if (t < 16) {
        slg[t] = (t < 14) ? lng[t] : 0.f;
        slb[t] = (t < 14) ? lnb[t] : 0.f;
    }
    __syncthreads();

    const size_t pair = (size_t)blockIdx.x * NW + w;
    const float c0v = g_c0[0];

    __half* sx   = stil + w * 1216;          // 16 rows x 72 halves
    float*  sxu1 = (float*)(sx + 1152);      // 16
    float*  sxu2 = sxu1 + 16;                // 16

    // ---- load x tile -> fp16 smem; zero rows 14,15 ----
    const float4* xg4 = (const float4*)(x + pair * 896);
    #pragma unroll
    for (int it = 0; it < 7; it++) {
        int k = l + 32 * it;
        float4 v = xg4[k];
        int row = k >> 4, c4 = k & 15;
        *(uint2*)(sx + row * 72 + c4 * 4) = make_uint2(h2u(v.x, v.y), h2u(v.z, v.w));
    }
    for (int i = l; i < 72; i += 32) ((uint32_t*)(sx + 14 * 72))[i] = 0u;
    __syncwarp();

    // ---- Y = x @ [A | u1 u2]  (4 k0 x 9 n0 = 36 MMAs) ----
    float dY[9][4] = {};
    #pragma unroll
    for (int k0 = 0; k0 < 4; k0++) {
        uint32_t a0 = *(const uint32_t*)(sx + g * 72 + k0 * 16 + 2 * tg);
        uint32_t a1 = *(const uint32_t*)(sx + (g + 8) * 72 + k0 * 16 + 2 * tg);
        uint32_t a2 = *(const uint32_t*)(sx + g * 72 + k0 * 16 + 2 * tg + 8);
        uint32_t a3 = *(const uint32_t*)(sx + (g + 8) * 72 + k0 * 16 + 2 * tg + 8);
        const uint2* pa = sPA + (k0 * 4 + tg) * 84 + g;
        #pragma unroll
        for (int n0 = 0; n0 < 9; n0++) {
            uint2 b = pa[n0 * 8];
            mma16(dY[n0], a0, a1, a2, a3, b.x, b.y);
        }
    }
    // dY[8] cols 64-71: tg==0 lanes hold (xu1, xu2) for rows g, g+8
    if (tg == 0) {
        sxu1[g] = dY[8][0]; sxu2[g] = dY[8][1];
        sxu1[g + 8] = dY[8][2]; sxu2[g + 8] = dY[8][3];
    }

    // ---- energy = y @ x^T  (8 MMAs); y A-frags are lane-local packs ----
    float e[2][4] = {};
    #pragma unroll
    for (int k0 = 0; k0 < 4; k0++) {
        uint32_t a0 = h2u(dY[2 * k0][0], dY[2 * k0][1]);
        uint32_t a1 = h2u(dY[2 * k0][2], dY[2 * k0][3]);
        uint32_t a2 = h2u(dY[2 * k0 + 1][0], dY[2 * k0 + 1][1]);
        uint32_t a3 = h2u(dY[2 * k0 + 1][2], dY[2 * k0 + 1][3]);
        #pragma unroll
        for (int nt = 0; nt < 2; nt++) {
            uint32_t b0 = *(const uint32_t*)(sx + (nt * 8 + g) * 72 + k0 * 16 + 2 * tg);
            uint32_t b1 = *(const uint32_t*)(sx + (nt * 8 + g) * 72 + k0 * 16 + 2 * tg + 8);
            mma16(e[nt], a0, a1, a2, a3, b0, b1);
        }
    }
    __syncwarp();   // sxu stores visible
    float et[2][4];
    {
        float xg0 = sxu1[g] + c0v, xg8 = sxu1[g + 8] + c0v;
        #pragma unroll
        for (int nt = 0; nt < 2; nt++) {
            int j0 = nt * 8 + 2 * tg;
            float u0 = sxu2[j0], u1v = sxu2[j0 + 1];
            et[nt][0] = e[nt][0] + xg0 + u0;
            et[nt][1] = e[nt][1] + xg0 + u1v;
            et[nt][2] = e[nt][2] + xg8 + u0;
            et[nt][3] = e[nt][3] + xg8 + u1v;
        }
    }

    // ---- mix = wc @ energy (2 MMAs); energy B-frags via quad shuffles ----
    float att0[2], att1[2], att2[2], att3[2];
    {
        uint32_t wa0 = *(const uint32_t*)(swch + g * 24 + 2 * tg);
        uint32_t wa1 = *(const uint32_t*)(swch + (g + 8) * 24 + 2 * tg);
        uint32_t wa2 = *(const uint32_t*)(swch + g * 24 + 2 * tg + 8);
        uint32_t wa3 = *(const uint32_t*)(swch + (g + 8) * 24 + 2 * tg + 8);
        const int s1 = 8 * tg + (g >> 1), s2 = s1 + 4;
        const bool podd = g & 1;
        float m[2][4] = {};
        #pragma unroll
        for (int nt = 0; nt < 2; nt++) {
            float f0 = __shfl_sync(FULLMASK, et[nt][0], s1);
            float f1 = __shfl_sync(FULLMASK, et[nt][1], s1);
            float f2 = __shfl_sync(FULLMASK, et[nt][2], s1);
            float f3 = __shfl_sync(FULLMASK, et[nt][3], s1);
            float h0 = __shfl_sync(FULLMASK, et[nt][0], s2);
            float h1 = __shfl_sync(FULLMASK, et[nt][1], s2);
            float h2v = __shfl_sync(FULLMASK, et[nt][2], s2);
            float h3 = __shfl_sync(FULLMASK, et[nt][3], s2);
            uint32_t b0 = h2u(podd ? f1 : f0, podd ? h1 : h0);
            uint32_t b1 = h2u(podd ? f3 : f2, podd ? h3 : h2v);
            mma16(m[nt], wa0, wa1, wa2, wa3, b0, b1);
        }
        // ---- LayerNorm + softmax in regs (quad reductions) ----
        const bool m3 = (tg == 3);   // cols 14,15
        float lg0 = slg[2 * tg], lg1 = slg[2 * tg + 1];
        float lg2 = slg[8 + 2 * tg], lg3 = slg[9 + 2 * tg];
        float lb0 = slb[2 * tg], lb1 = slb[2 * tg + 1];
        float lb2 = slb[8 + 2 * tg], lb3 = slb[9 + 2 * tg];
        #pragma unroll
        for (int rr = 0; rr < 2; rr++) {
            float v0 = m[0][2 * rr], v1 = m[0][2 * rr + 1];
            float v2 = m[1][2 * rr], v3 = m[1][2 * rr + 1];
            float s = v0 + v1 + (m3 ? 0.f : (v2 + v3));
            s += __shfl_xor_sync(FULLMASK, s, 1);
            s += __shfl_xor_sync(FULLMASK, s, 2);
            float mu = s * (1.f / 14.f);
            float d0 = v0 - mu, d1 = v1 - mu, d2 = v2 - mu, d3 = v3 - mu;
            float q = d0 * d0 + d1 * d1 + (m3 ? 0.f : (d2 * d2 + d3 * d3));
            q += __shfl_xor_sync(FULLMASK, q, 1);
            q += __shfl_xor_sync(FULLMASK, q, 2);
            float rsv = rsqrtf(q * (1.f / 14.f) + 1e-5f);
            float t0 = (d0 * rsv * lg0 + lb0) * 0.125f;
            float t1 = (d1 * rsv * lg1 + lb1) * 0.125f;
            float t2 = (d2 * rsv * lg2 + lb2) * 0.125f;
            float t3 = (d3 * rsv * lg3 + lb3) * 0.125f;
            float mx = fmaxf(fmaxf(t0, t1), m3 ? -1e30f : fmaxf(t2, t3));
            mx = fmaxf(mx, __shfl_xor_sync(FULLMASK, mx, 1));
            mx = fmaxf(mx, __shfl_xor_sync(FULLMASK, mx, 2));
            float e0 = __expf(t0 - mx), e1 = __expf(t1 - mx);
            float e2 = m3 ? 0.f : __expf(t2 - mx);
            float e3 = m3 ? 0.f : __expf(t3 - mx);
            float ss = e0 + e1 + e2 + e3;
            ss += __shfl_xor_sync(FULLMASK, ss, 1);
            ss += __shfl_xor_sync(FULLMASK, ss, 2);
            float inv = 1.f / ss;
            att0[rr] = e0 * inv; att1[rr] = e1 * inv;
            att2[rr] = e2 * inv; att3[rr] = e3 * inv;
        }
    }
    // att C-frag -> A-frag: lane-local identity packs
    uint32_t aa0 = h2u(att0[0], att1[0]);
    uint32_t aa1 = h2u(att0[1], att1[1]);
    uint32_t aa2 = h2u(att2[0], att3[0]);
    uint32_t aa3 = h2u(att2[1], att3[1]);

    // ---- vT = Wv-as-A @ x-as-B, fused with out = att @ v  (32 + 8 MMAs) ----
    float* og = out + pair * 896;
    #pragma unroll
    for (int mt = 0; mt < 4; mt++) {
        float dv0[4] = {}, dv1[4] = {};
        #pragma unroll
        for (int k0 = 0; k0 < 4; k0++) {
            const uint2* pw = sPW + (mt * 8 + g) * 36 + 8 * k0 + tg;
            uint2 A01 = pw[0];
            uint2 A23 = pw[4];
            uint32_t b0 = *(const uint32_t*)(sx + g * 72 + k0 * 16 + 2 * tg);
            uint32_t b1 = *(const uint32_t*)(sx + g * 72 + k0 * 16 + 2 * tg + 8);
            mma16(dv0, A01.x, A01.y, A23.x, A23.y, b0, b1);
            uint32_t c0_ = *(const uint32_t*)(sx + (g + 8) * 72 + k0 * 16 + 2 * tg);
            uint32_t c1_ = *(const uint32_t*)(sx + (g + 8) * 72 + k0 * 16 + 2 * tg + 8);
            mma16(dv1, A01.x, A01.y, A23.x, A23.y, c0_, c1_);
        }
        // out columns 16mt..16mt+15: vT C-frags ARE the needed B-frags
        #pragma unroll
        for (int p = 0; p < 2; p++) {
            uint32_t b0 = h2u(dv0[2 * p], dv0[2 * p + 1]);
            uint32_t b1 = h2u(dv1[2 * p], dv1[2 * p + 1]);
            float od[4] = {};
            mma16(od, aa0, aa1, aa2, aa3, b0, b1);
            int cc = (2 * mt + p) * 8 + 2 * tg;
            float2 bb = *(const float2*)(sbv + cc);
            *(float2*)(og + g * 64 + cc) = make_float2(od[0] + bb.x, od[1] + bb.y);
            if (g < 6)
                *(float2*)(og + (g + 8) * 64 + cc) =
                    make_float2(od[2] + bb.x, od[3] + bb.y);
        }
    }
}

// ---------------------------------------------------------------------------
extern "C" void kernel_launch(void* const* d_in, const int* in_sizes, int n_in,
                              void* d_out, int out_size) {
    const float* x   = (const float*)d_in[0];
    const float* wc  = (const float*)d_in[1];
    const float* Wq  = (const float*)d_in[2];
    const float* bq  = (const float*)d_in[3];
    const float* Wk  = (const float*)d_in[4];
    const float* bk  = (const float*)d_in[5];
    const float* Wv  = (const float*)d_in[6];
    const float* bv  = (const float*)d_in[7];
    const float* lng = (const float*)d_in[8];
    const float* lnb = (const float*)d_in[9];
    float* out = (float*)d_out;

    cudaFuncSetAttribute(attn_kernel, cudaFuncAttributeMaxDynamicSharedMemorySize,
                         SMEM_BYTES);

    prep_kernel<<<1, 256>>>(Wq, bq, Wk, bk, Wv, wc);
    attn_kernel<<<8192, 32 * NW, SMEM_BYTES>>>(x, bv, lng, lnb, out);
}